// round 3
// baseline (speedup 1.0000x reference)
#include <cuda_runtime.h>

#define Bsz   16
#define Cch   32
#define Himg  256
#define Wimg  256

#define TILE_H 16
#define TILE_W 32
#define HALO_H 18
#define HALO_W 36   // padded to keep rows 16B-aligned (only 34 cols meaningful)

#define THREADS 512

#define WS_STRIDE 36                       // 32 co + pad; multiple of 4 -> 16B-aligned co groups
#define XS_ELEMS  (Cch * HALO_H * HALO_W)  // 20736 floats
#define WS_ELEMS  (Cch * 9 * WS_STRIDE)    // 10368 floats
#define SMEM_BYTES ((XS_ELEMS + WS_ELEMS) * 4)   // ~124.4 KB

// Scratch for the intermediate activation h (pass1 output / pass2 input).
__device__ float g_h[Bsz * Cch * Himg * Wimg];

// ---- f32x2 packed helpers (sm_103a dual-fp32 pipe) ----
__device__ __forceinline__ unsigned long long pack2_dup(float v) {
    unsigned long long r;
    asm("mov.b64 %0, {%1, %1};" : "=l"(r) : "f"(v));
    return r;
}
__device__ __forceinline__ void fma2(unsigned long long& d,
                                     unsigned long long a,
                                     unsigned long long b) {
    asm("fma.rn.f32x2 %0, %1, %2, %0;" : "+l"(d) : "l"(a), "l"(b));
}
__device__ __forceinline__ void unpack2(float& lo, float& hi, unsigned long long v) {
    asm("mov.b64 {%0, %1}, %2;" : "=f"(lo), "=f"(hi) : "l"(v));
}

template <bool SECOND>
__global__ __launch_bounds__(THREADS, 1)
void moe_conv_kernel(const float* __restrict__ x,     // original input [B,C,H,W]
                     const float* __restrict__ w,     // [C,C,3,3] OIHW
                     const float* __restrict__ bias,  // [C]
                     const float* __restrict__ gate,  // [B,C]
                     float* __restrict__ out)         // final output (pass2 only)
{
    extern __shared__ float sm[];
    float* xs = sm;              // [ci][row][col] : Cch x HALO_H x HALO_W
    float* ws = sm + XS_ELEMS;   // [ci*9+tap][co] stride WS_STRIDE

    const int bx  = blockIdx.x;          // 0..7   (W tiles)
    const int by  = blockIdx.y;          // 0..15  (H tiles)
    const int bb  = blockIdx.z;          // 0..15  (batch)
    const int tid = threadIdx.x;

    const int x0 = bx * TILE_W;
    const int y0 = by * TILE_H;

    // ---- load weights, transposed to [ci*9+tap][co] ----
    #pragma unroll 1
    for (int i = tid; i < Cch * Cch * 9; i += THREADS) {
        int co  = i / (Cch * 9);
        int rem = i - co * (Cch * 9);    // ci*9 + tap
        ws[rem * WS_STRIDE + co] = w[i];
    }

    // ---- load input tile (x for pass1, h for pass2) with zero halo/pad ----
    const float* inb = (SECOND ? g_h : x) + (size_t)bb * Cch * Himg * Wimg;
    #pragma unroll 1
    for (int i = tid; i < XS_ELEMS; i += THREADS) {
        int ci = i / (HALO_H * HALO_W);
        int r  = (i / HALO_W) % HALO_H;
        int c  = i % HALO_W;
        int gy = y0 + r - 1;
        int gx = x0 + c - 1;
        float v = 0.0f;
        if ((unsigned)gy < (unsigned)Himg && (unsigned)gx < (unsigned)Wimg)
            v = inb[(size_t)ci * (Himg * Wimg) + gy * Wimg + gx];
        xs[i] = v;
    }
    __syncthreads();

    // ---- thread tile: 4 output channels x 8 pixels, f32x2-packed over co ----
    const int cg  = tid & 7;         // co group (8 groups of 4)
    const int pg  = tid >> 3;        // pixel group (64 groups of 8)
    const int r   = pg >> 2;         // tile row 0..15
    const int cb  = (pg & 3) * 8;    // tile col base 0/8/16/24
    const int co0 = cg * 4;

    // accp[p][j] = { acc[co0+2p][j], acc[co0+2p+1][j] }
    unsigned long long accp[2][8];
    #pragma unroll
    for (int p = 0; p < 2; p++)
        #pragma unroll
        for (int j = 0; j < 8; j++)
            accp[p][j] = 0ULL;

    #pragma unroll 2
    for (int ci = 0; ci < Cch; ci++) {
        const float* xci = xs + ci * (HALO_H * HALO_W);
        #pragma unroll
        for (int dy = 0; dy < 3; dy++) {
            // 12 floats (16B-aligned, 3x LDS.128); only [0..9] used
            const float4* xr4 = reinterpret_cast<const float4*>(
                xci + (r + dy) * HALO_W + cb);
            float4 a0 = xr4[0], a1 = xr4[1], a2 = xr4[2];
            float xv[12] = {a0.x, a0.y, a0.z, a0.w,
                            a1.x, a1.y, a1.z, a1.w,
                            a2.x, a2.y, a2.z, a2.w};

            unsigned long long xd[10];
            #pragma unroll
            for (int k = 0; k < 10; k++) xd[k] = pack2_dup(xv[k]);

            #pragma unroll
            for (int dx = 0; dx < 3; dx++) {
                // {w[co0],w[co0+1]} and {w[co0+2],w[co0+3]} via one LDS.128
                const ulonglong2* wp2 = reinterpret_cast<const ulonglong2*>(
                    ws + (ci * 9 + dy * 3 + dx) * WS_STRIDE + co0);
                ulonglong2 wv = *wp2;
                #pragma unroll
                for (int j = 0; j < 8; j++) {
                    fma2(accp[0][j], wv.x, xd[dx + j]);
                    fma2(accp[1][j], wv.y, xd[dx + j]);
                }
            }
        }
    }

    // ---- unpack ----
    float acc[4][8];
    #pragma unroll
    for (int p = 0; p < 2; p++)
        #pragma unroll
        for (int j = 0; j < 8; j++)
            unpack2(acc[2 * p][j], acc[2 * p + 1][j], accp[p][j]);

    // ---- epilogue: bias, gate, relu, (+residual), store ----
    const int oy = y0 + r;
    const int ox = x0 + cb;
    float* dst = SECOND ? out : g_h;

    #pragma unroll
    for (int a = 0; a < 4; a++) {
        int co = co0 + a;
        float bi = bias[co];
        float g  = gate[bb * Cch + co];
        g = (g > 0.0f) ? g : 0.0f;

        size_t base = (((size_t)bb * Cch + co) * Himg + oy) * Wimg + ox;

        float t[8];
        #pragma unroll
        for (int j = 0; j < 8; j++) {
            float v = (acc[a][j] + bi) * g;
            t[j] = (v > 0.0f) ? v : 0.0f;
        }

        if (SECOND) {
            const float4* rx = reinterpret_cast<const float4*>(x + base);
            float4 r0 = rx[0], r1 = rx[1];
            t[0] += r0.x; t[1] += r0.y; t[2] += r0.z; t[3] += r0.w;
            t[4] += r1.x; t[5] += r1.y; t[6] += r1.z; t[7] += r1.w;
        }

        float4* op = reinterpret_cast<float4*>(dst + base);
        op[0] = make_float4(t[0], t[1], t[2], t[3]);
        op[1] = make_float4(t[4], t[5], t[6], t[7]);
    }
}

extern "C" void kernel_launch(void* const* d_in, const int* in_sizes, int n_in,
                              void* d_out, int out_size)
{
    const float* x    = (const float*)d_in[0];
    const float* gate = (const float*)d_in[1];
    const float* w1   = (const float*)d_in[2];
    const float* b1   = (const float*)d_in[3];
    const float* w2   = (const float*)d_in[4];
    const float* b2   = (const float*)d_in[5];
    float*       out  = (float*)d_out;
    (void)in_sizes; (void)n_in; (void)out_size;

    cudaFuncSetAttribute(moe_conv_kernel<false>,
                         cudaFuncAttributeMaxDynamicSharedMemorySize, SMEM_BYTES);
    cudaFuncSetAttribute(moe_conv_kernel<true>,
                         cudaFuncAttributeMaxDynamicSharedMemorySize, SMEM_BYTES);

    dim3 grid(Wimg / TILE_W, Himg / TILE_H, Bsz);   // 8 x 16 x 16 = 2048 CTAs

    // pass 1: h = relu((conv(x,w1)+b1)*g)   -> g_h
    moe_conv_kernel<false><<<grid, THREADS, SMEM_BYTES>>>(x, w1, b1, gate, nullptr);
    // pass 2: out = relu((conv(h,w2)+b2)*g) + x
    moe_conv_kernel<true><<<grid, THREADS, SMEM_BYTES>>>(x, w2, b2, gate, out);
}

// round 5
// speedup vs baseline: 2.2526x; 2.2526x over previous
#include <cuda_runtime.h>
#include <cuda_bf16.h>
#include <cstdint>

#define Bsz  16
#define Cch  32
#define Himg 256
#define Wimg 256

#define TILE_H 16
#define TILE_W 32
#define HALO_W 34
#define NPIX   612            // 18 rows x 34 cols

#define THREADS 512

// smem byte offsets
#define A_OFF    0
#define WH_OFF   (NPIX * 128)            // 78336
#define WL_OFF   (WH_OFF + 9 * 2048)     // 96768
#define BIAS_OFF (WL_OFF + 9 * 2048)     // 115200
#define GATE_OFF (BIAS_OFF + 128)
#define SMEM_BYTES (GATE_OFF + 128)      // 115456

// h scratch: per pixel 32 bf16 = 16 uint32 (hi plane), + lo plane. 128 MB.
#define HPIX   (16u * 65536u)            // Bsz*Himg*Wimg
#define HLO32  (HPIX * 16u)              // uint32 offset of lo plane
__device__ uint32_t g_h[2ull * HPIX * 16u];

// ---------------- helpers ----------------
__device__ __forceinline__ uint32_t smem_u32(const void* p) {
    uint32_t a;
    asm("{ .reg .u64 t; cvta.to.shared.u64 t, %1; cvt.u32.u64 %0, t; }"
        : "=r"(a) : "l"(p));
    return a;
}
__device__ __forceinline__ void ldmx4(uint32_t* d, uint32_t a) {
    asm volatile("ldmatrix.sync.aligned.m8n8.x4.shared.b16 {%0,%1,%2,%3}, [%4];"
                 : "=r"(d[0]), "=r"(d[1]), "=r"(d[2]), "=r"(d[3]) : "r"(a));
}
__device__ __forceinline__ void ldmx2t(uint32_t* d, uint32_t a) {
    asm volatile("ldmatrix.sync.aligned.m8n8.x2.trans.shared.b16 {%0,%1}, [%2];"
                 : "=r"(d[0]), "=r"(d[1]) : "r"(a));
}
__device__ __forceinline__ void mma16816(float* c, const uint32_t* a, const uint32_t* b) {
    asm volatile("mma.sync.aligned.m16n8k16.row.col.f32.bf16.bf16.f32 "
                 "{%0,%1,%2,%3}, {%4,%5,%6,%7}, {%8,%9}, {%0,%1,%2,%3};"
                 : "+f"(c[0]), "+f"(c[1]), "+f"(c[2]), "+f"(c[3])
                 : "r"(a[0]), "r"(a[1]), "r"(a[2]), "r"(a[3]),
                   "r"(b[0]), "r"(b[1]));
}

// A-tile swizzled byte offset: pixel p, 16B-granule kc (0..7; hi=0..3, lo=4..7)
__device__ __forceinline__ uint32_t a_byte(int p, int kc) {
    return (uint32_t)(p * 128 + (((kc + p) & 7) << 4));
}
// W-tile swizzled byte offset within one tap region: k-row ci, n-block nb (0..3)
__device__ __forceinline__ uint32_t w_byte(int ci, int nb) {
    return (uint32_t)(ci * 64 + (((nb + ((ci >> 1) & 3)) & 3) << 4));
}

// ---------------- kernel ----------------
template <bool SECOND>
__global__ __launch_bounds__(THREADS, 1)
void conv_hmma(const float* __restrict__ x,
               const float* __restrict__ w,
               const float* __restrict__ bias,
               const float* __restrict__ gate,
               float* __restrict__ out)
{
    extern __shared__ char sm[];
    const uint32_t smb = smem_u32(sm);
    const int tid = threadIdx.x;
    const int b  = blockIdx.z;
    const int y0 = blockIdx.y * TILE_H;
    const int x0 = blockIdx.x * TILE_W;

    // ---- weights -> [tap][ci][co] bf16 hi/lo, swizzled ----
    for (int i = tid; i < Cch * Cch * 9; i += THREADS) {
        int co = i / 288, rem = i - co * 288;
        int ci = rem / 9, tap = rem - ci * 9;
        float v = w[i];
        __nv_bfloat16 hh = __float2bfloat16(v);
        __nv_bfloat16 ll = __float2bfloat16(v - __bfloat162float(hh));
        uint32_t byte = tap * 2048 + w_byte(ci, co >> 3) + ((co & 7) << 1);
        *(__nv_bfloat16*)(sm + WH_OFF + byte) = hh;
        *(__nv_bfloat16*)(sm + WL_OFF + byte) = ll;
    }
    if (tid < 32) {
        ((float*)(sm + BIAS_OFF))[tid] = bias[tid];
        float g = gate[b * 32 + tid];
        ((float*)(sm + GATE_OFF))[tid] = (g > 0.0f) ? g : 0.0f;
    }

    // ---- A tile fill (channels-last, hi/lo, swizzled) ----
    if (!SECOND) {
        for (int i = tid; i < NPIX * 32; i += THREADS) {
            int ci = i / NPIX, p = i - ci * NPIX;
            int gy = y0 - 1 + p / HALO_W;
            int gx = x0 - 1 + p % HALO_W;
            float v = 0.0f;
            if ((unsigned)gy < (unsigned)Himg && (unsigned)gx < (unsigned)Wimg)
                v = x[(((size_t)b * Cch + ci) * Himg + gy) * Wimg + gx];
            __nv_bfloat16 hh = __float2bfloat16(v);
            __nv_bfloat16 ll = __float2bfloat16(v - __bfloat162float(hh));
            int sub = (ci & 7) << 1;
            *(__nv_bfloat16*)(sm + A_OFF + a_byte(p, ci >> 3) + sub)       = hh;
            *(__nv_bfloat16*)(sm + A_OFF + a_byte(p, 4 + (ci >> 3)) + sub) = ll;
        }
    } else {
        const uint4* gh4 = (const uint4*)g_h;
        for (int i = tid; i < NPIX * 4; i += THREADS) {
            int p = i >> 2, chunk = i & 3;
            int gy = y0 - 1 + p / HALO_W;
            int gx = x0 - 1 + p % HALO_W;
            uint4 vh = make_uint4(0, 0, 0, 0), vl = vh;
            if ((unsigned)gy < (unsigned)Himg && (unsigned)gx < (unsigned)Wimg) {
                size_t pix = (size_t)b * 65536 + gy * 256 + gx;
                vh = gh4[pix * 4 + chunk];
                vl = gh4[pix * 4 + chunk + (HLO32 >> 2)];
            }
            *(uint4*)(sm + A_OFF + a_byte(p, chunk))     = vh;
            *(uint4*)(sm + A_OFF + a_byte(p, 4 + chunk)) = vl;
        }
    }
    __syncthreads();

    // ---- compute: warp = output row; 2 m-blocks x 4 n-blocks ----
    const int wid  = tid >> 5;
    const int lane = tid & 31;
    const int r    = wid;                 // output row 0..15
    const int lm   = lane & 15;           // ldmatrix A row lane
    const int ksel = (lane >> 4) & 1;     // ldmatrix A k-chunk select

    float acc[2][4][4];
    #pragma unroll
    for (int mb = 0; mb < 2; mb++)
        #pragma unroll
        for (int nb = 0; nb < 4; nb++)
            #pragma unroll
            for (int e = 0; e < 4; e++)
                acc[mb][nb][e] = 0.0f;

    #pragma unroll
    for (int dy = 0; dy < 3; dy++) {
        #pragma unroll
        for (int dx = 0; dx < 3; dx++) {
            const int tap  = dy * 3 + dx;
            const int pbase = (r + dy) * HALO_W + dx;
            #pragma unroll
            for (int kb = 0; kb < 2; kb++) {
                uint32_t Ah[2][4], Al[2][4];
                #pragma unroll
                for (int mb = 0; mb < 2; mb++) {
                    int p = pbase + mb * 16 + lm;
                    ldmx4(Ah[mb], smb + A_OFF + a_byte(p, kb * 2 + ksel));
                    ldmx4(Al[mb], smb + A_OFF + a_byte(p, 4 + kb * 2 + ksel));
                }
                const int ci = kb * 16 + lm;
                #pragma unroll
                for (int nb = 0; nb < 4; nb++) {
                    uint32_t bh[2], bl[2];
                    uint32_t wb = tap * 2048 + w_byte(ci, nb);
                    ldmx2t(bh, smb + WH_OFF + wb);
                    ldmx2t(bl, smb + WL_OFF + wb);
                    #pragma unroll
                    for (int mb = 0; mb < 2; mb++) {
                        mma16816(acc[mb][nb], Ah[mb], bh);
                        mma16816(acc[mb][nb], Al[mb], bh);
                        mma16816(acc[mb][nb], Ah[mb], bl);
                    }
                }
            }
        }
    }

    // ---- epilogue ----
    const float* bs = (const float*)(sm + BIAS_OFF);
    const float* gs = (const float*)(sm + GATE_OFF);
    const int grp = lane >> 2, tig = lane & 3;
    const int y = y0 + r;

    #pragma unroll
    for (int mb = 0; mb < 2; mb++) {
        #pragma unroll
        for (int half = 0; half < 2; half++) {
            const int xg = x0 + mb * 16 + grp + half * 8;
            #pragma unroll
            for (int nb = 0; nb < 4; nb++) {
                const int co = nb * 8 + tig * 2;
                float v0 = acc[mb][nb][half * 2 + 0];
                float v1 = acc[mb][nb][half * 2 + 1];
                float t0 = fmaxf((v0 + bs[co])     * gs[co],     0.0f);
                float t1 = fmaxf((v1 + bs[co + 1]) * gs[co + 1], 0.0f);
                if (SECOND) {
                    size_t i0 = (((size_t)b * Cch + co)     * Himg + y) * Wimg + xg;
                    size_t i1 = (((size_t)b * Cch + co + 1) * Himg + y) * Wimg + xg;
                    out[i0] = t0 + x[i0];
                    out[i1] = t1 + x[i1];
                } else {
                    __nv_bfloat16 h0 = __float2bfloat16(t0);
                    __nv_bfloat16 h1 = __float2bfloat16(t1);
                    __nv_bfloat16 l0 = __float2bfloat16(t0 - __bfloat162float(h0));
                    __nv_bfloat16 l1 = __float2bfloat16(t1 - __bfloat162float(h1));
                    uint32_t uh = (uint32_t)__bfloat16_as_ushort(h0)
                                | ((uint32_t)__bfloat16_as_ushort(h1) << 16);
                    uint32_t ul = (uint32_t)__bfloat16_as_ushort(l0)
                                | ((uint32_t)__bfloat16_as_ushort(l1) << 16);
                    size_t pix = (size_t)b * 65536 + y * 256 + xg;
                    g_h[pix * 16 + (co >> 1)]         = uh;
                    g_h[pix * 16 + (co >> 1) + HLO32] = ul;
                }
            }
        }
    }
}

extern "C" void kernel_launch(void* const* d_in, const int* in_sizes, int n_in,
                              void* d_out, int out_size)
{
    const float* x    = (const float*)d_in[0];
    const float* gate = (const float*)d_in[1];
    const float* w1   = (const float*)d_in[2];
    const float* b1   = (const float*)d_in[3];
    const float* w2   = (const float*)d_in[4];
    const float* b2   = (const float*)d_in[5];
    float*       out  = (float*)d_out;
    (void)in_sizes; (void)n_in; (void)out_size;

    cudaFuncSetAttribute(conv_hmma<false>,
                         cudaFuncAttributeMaxDynamicSharedMemorySize, SMEM_BYTES);
    cudaFuncSetAttribute(conv_hmma<true>,
                         cudaFuncAttributeMaxDynamicSharedMemorySize, SMEM_BYTES);

    dim3 grid(Wimg / TILE_W, Himg / TILE_H, Bsz);   // 8 x 16 x 16 = 2048 CTAs

    conv_hmma<false><<<grid, THREADS, SMEM_BYTES>>>(x, w1, b1, gate, nullptr);
    conv_hmma<true ><<<grid, THREADS, SMEM_BYTES>>>(x, w2, b2, gate, out);
}